// round 2
// baseline (speedup 1.0000x reference)
#include <cuda_runtime.h>
#include <cuda_bf16.h>

#define N    4096
#define D    512
#define BM   128
#define BN   128
#define BK   16
#define TM   8
#define TN   8
#define NTHREADS 256
#define AS_LD (BM + 4)   // pad to reduce smem store conflicts on transposed fill
#define MARGIN 40.0f

// Scratch: per-row running min (positives) / max (negatives), stored as
// order-preserving encoded unsigned so atomicMin/atomicMax work on floats.
__device__ unsigned g_min_enc[N];
__device__ unsigned g_max_enc[N];

__device__ __forceinline__ unsigned enc_f(float f) {
    unsigned u = __float_as_uint(f);
    return (u & 0x80000000u) ? ~u : (u | 0x80000000u);
}
__device__ __forceinline__ float dec_f(unsigned e) {
    unsigned u = (e & 0x80000000u) ? (e ^ 0x80000000u) : ~e;
    return __uint_as_float(u);
}

__global__ void init_kernel() {
    int i = blockIdx.x * blockDim.x + threadIdx.x;
    if (i < N) {
        g_min_enc[i] = enc_f(3.402823466e38f);    // +FLT_MAX ("big")
        g_max_enc[i] = enc_f(-3.402823466e38f);   // -FLT_MAX
    }
}

// Fused Gram + masked min/max. Each block computes a 128x128 tile of
// corr = feat @ feat^T and folds it into per-row min/max immediately.
__global__ __launch_bounds__(NTHREADS, 2)
void corr_kernel(const float* __restrict__ feat,
                 const int* __restrict__ targets) {   // NOTE: jax x64 disabled -> int32
    __shared__ float As[BK][AS_LD];
    __shared__ float Bs[BK][AS_LD];
    __shared__ int ti[BM];
    __shared__ int tj[BN];

    const int i0 = blockIdx.y * BM;
    const int j0 = blockIdx.x * BN;
    const int tid = threadIdx.x;
    const int tx = tid & 15;   // 0..15  -> column group
    const int ty = tid >> 4;   // 0..15  -> row group

    // load class labels for this tile
    if (tid < BM) ti[tid] = targets[i0 + tid];
    else          tj[tid - BM] = targets[j0 + (tid - BM)];

    float acc[TM][TN];
#pragma unroll
    for (int m = 0; m < TM; m++)
#pragma unroll
        for (int n = 0; n < TN; n++) acc[m][n] = 0.0f;

    for (int k0 = 0; k0 < D; k0 += BK) {
        // Fill As/Bs (transposed): 128 rows x 16 cols each = 512 float4s,
        // 256 threads -> 2 float4 per array per thread.
#pragma unroll
        for (int l = 0; l < 2; l++) {
            int t   = tid + l * NTHREADS;   // 0..511
            int row = t >> 2;               // 0..127
            int c4  = (t & 3) * 4;          // 0,4,8,12
            float4 a = *(const float4*)(feat + (long)(i0 + row) * D + k0 + c4);
            As[c4 + 0][row] = a.x; As[c4 + 1][row] = a.y;
            As[c4 + 2][row] = a.z; As[c4 + 3][row] = a.w;
            float4 b = *(const float4*)(feat + (long)(j0 + row) * D + k0 + c4);
            Bs[c4 + 0][row] = b.x; Bs[c4 + 1][row] = b.y;
            Bs[c4 + 2][row] = b.z; Bs[c4 + 3][row] = b.w;
        }
        __syncthreads();

#pragma unroll
        for (int k = 0; k < BK; k++) {
            float af[TM], bf[TN];
#pragma unroll
            for (int m = 0; m < TM; m++) af[m] = As[k][ty * TM + m];
#pragma unroll
            for (int n = 0; n < TN; n++) bf[n] = Bs[k][tx * TN + n];
#pragma unroll
            for (int m = 0; m < TM; m++)
#pragma unroll
                for (int n = 0; n < TN; n++)
                    acc[m][n] = fmaf(af[m], bf[n], acc[m][n]);
        }
        __syncthreads();
    }

    // Epilogue: masked min/max per row, reduce across the 16 threads (tx)
    // that share the same 8 rows. Those 16 threads are a half-warp:
    // lane = (ty&1)*16 + tx, so xor-shuffles 1,2,4,8 stay within the group.
#pragma unroll
    for (int m = 0; m < TM; m++) {
        int row = ty * TM + m;
        int cls = ti[row];
        float vmin =  3.402823466e38f;
        float vmax = -3.402823466e38f;
#pragma unroll
        for (int n = 0; n < TN; n++) {
            int col = tx * TN + n;
            float v = acc[m][n];
            if (cls == tj[col]) vmin = fminf(vmin, v);
            else                vmax = fmaxf(vmax, v);
        }
#pragma unroll
        for (int off = 1; off < 16; off <<= 1) {
            vmin = fminf(vmin, __shfl_xor_sync(0xffffffffu, vmin, off));
            vmax = fmaxf(vmax, __shfl_xor_sync(0xffffffffu, vmax, off));
        }
        if (tx == 0) {
            atomicMin(&g_min_enc[i0 + row], enc_f(vmin));
            atomicMax(&g_max_enc[i0 + row], enc_f(vmax));
        }
    }
}

__global__ void loss_kernel(float* __restrict__ out) {
    __shared__ float red[256];
    float s = 0.0f;
    for (int i = threadIdx.x; i < N; i += 256) {
        float ap = dec_f(g_min_enc[i]);
        float an = dec_f(g_max_enc[i]);
        float v = an - ap + MARGIN;
        s += (v > 0.0f) ? v : 0.0f;
    }
    red[threadIdx.x] = s;
    __syncthreads();
    for (int o = 128; o > 0; o >>= 1) {
        if (threadIdx.x < o) red[threadIdx.x] += red[threadIdx.x + o];
        __syncthreads();
    }
    if (threadIdx.x == 0) out[0] = red[0] * (1.0f / (float)N);
}

extern "C" void kernel_launch(void* const* d_in, const int* in_sizes, int n_in,
                              void* d_out, int out_size) {
    const float* feat    = (const float*)d_in[0];
    const int*   targets = (const int*)d_in[1];
    float*       out     = (float*)d_out;

    init_kernel<<<(N + 255) / 256, 256>>>();
    dim3 grid(N / BN, N / BM);
    corr_kernel<<<grid, NTHREADS>>>(feat, targets);
    loss_kernel<<<1, 256>>>(out);
}

// round 4
// speedup vs baseline: 2.6167x; 2.6167x over previous
#include <cuda_runtime.h>
#include <cuda_bf16.h>
#include <cstdint>

#define NR   4096
#define DD   512
#define BM   128
#define BN   128
#define KS   32                 // bf16 k-elems per pipeline stage
#define NSTG 4
#define NTH  256
#define NPASS 3
#define STAGES_TOTAL (NPASS * (DD / KS))   // 48
#define STAGE_BYTES  16384      // A 8KB + B 8KB
#define SMEM_LABELS  (NSTG * STAGE_BYTES)  // 65536
#define SMEM_TOTAL   (SMEM_LABELS + 1024)
#define MARGIN 40.0f

// ---------------- device scratch (no allocations allowed) ----------------
__device__ __nv_bfloat16 g_hi[NR * DD];
__device__ __nv_bfloat16 g_lo[NR * DD];
__device__ unsigned g_min_enc[NR];
__device__ unsigned g_max_enc[NR];

// ---------------- helpers ----------------
__device__ __forceinline__ unsigned enc_f(float f) {
    unsigned u = __float_as_uint(f);
    return (u & 0x80000000u) ? ~u : (u | 0x80000000u);
}
__device__ __forceinline__ float dec_f(unsigned e) {
    unsigned u = (e & 0x80000000u) ? (e ^ 0x80000000u) : ~e;
    return __uint_as_float(u);
}
__device__ __forceinline__ uint32_t smem_u32(const void* p) {
    uint32_t a;
    asm("{ .reg .u64 t; cvta.to.shared.u64 t, %1; cvt.u32.u64 %0, t; }" : "=r"(a) : "l"(p));
    return a;
}

#define CP16(smem_addr, gptr) \
    asm volatile("cp.async.cg.shared.global [%0], [%1], 16;" :: "r"(smem_addr), "l"(gptr))
#define CP_COMMIT() asm volatile("cp.async.commit_group;" ::: "memory")
#define CP_WAIT(n)  asm volatile("cp.async.wait_group %0;" :: "n"(n) : "memory")

#define LDSM4(r, addr) \
    asm volatile("ldmatrix.sync.aligned.m8n8.x4.shared.b16 {%0,%1,%2,%3}, [%4];" \
                 : "=r"((r)[0]), "=r"((r)[1]), "=r"((r)[2]), "=r"((r)[3]) : "r"(addr))

#define MMA_BF16(d, a, b0, b1) \
    asm volatile("mma.sync.aligned.m16n8k16.row.col.f32.bf16.bf16.f32 " \
                 "{%0,%1,%2,%3}, {%4,%5,%6,%7}, {%8,%9}, {%0,%1,%2,%3};" \
                 : "+f"((d)[0]), "+f"((d)[1]), "+f"((d)[2]), "+f"((d)[3]) \
                 : "r"((a)[0]), "r"((a)[1]), "r"((a)[2]), "r"((a)[3]), "r"(b0), "r"(b1))

// XOR swizzle: chunk c in {0..3} (16B each) within a 64B row r
__device__ __forceinline__ uint32_t sw_off(int r, int c) {
    return (uint32_t)(r * 64 + ((c ^ ((r >> 1) & 3)) << 4));
}

// ---------------- kernels ----------------
__global__ void init_kernel() {
    int i = blockIdx.x * blockDim.x + threadIdx.x;
    if (i < NR) {
        g_min_enc[i] = enc_f(3.402823466e38f);
        g_max_enc[i] = enc_f(-3.402823466e38f);
    }
}

__global__ void split_kernel(const float* __restrict__ feat) {
    int i = blockIdx.x * blockDim.x + threadIdx.x;   // over N*D/4 float4s
    float4 v = ((const float4*)feat)[i];
    ushort4 h, l;
    __nv_bfloat16 b;
    b = __float2bfloat16(v.x); h.x = __bfloat16_as_ushort(b);
    l.x = __bfloat16_as_ushort(__float2bfloat16(v.x - __bfloat162float(b)));
    b = __float2bfloat16(v.y); h.y = __bfloat16_as_ushort(b);
    l.y = __bfloat16_as_ushort(__float2bfloat16(v.y - __bfloat162float(b)));
    b = __float2bfloat16(v.z); h.z = __bfloat16_as_ushort(b);
    l.z = __bfloat16_as_ushort(__float2bfloat16(v.z - __bfloat162float(b)));
    b = __float2bfloat16(v.w); h.w = __bfloat16_as_ushort(b);
    l.w = __bfloat16_as_ushort(__float2bfloat16(v.w - __bfloat162float(b)));
    ((ushort4*)g_hi)[i] = h;
    ((ushort4*)g_lo)[i] = l;
}

__global__ __launch_bounds__(NTH, 2)
void corr_kernel(const int* __restrict__ targets) {
    extern __shared__ char smem[];
    const uint32_t sb = smem_u32(smem);
    int* ti_s = (int*)(smem + SMEM_LABELS);
    int* tj_s = ti_s + BM;

    const int tid  = threadIdx.x;
    const int lane = tid & 31;
    const int wid  = tid >> 5;
    const int wm   = wid & 1;    // 0..1  (64-row band)
    const int wn   = wid >> 1;   // 0..3  (32-col band)
    const int i0 = blockIdx.y * BM;
    const int j0 = blockIdx.x * BN;

    if (tid < BM) ti_s[tid] = targets[i0 + tid];
    else          tj_s[tid - BM] = targets[j0 + (tid - BM)];

    float acc[4][4][4];
#pragma unroll
    for (int mt = 0; mt < 4; mt++)
#pragma unroll
        for (int nt = 0; nt < 4; nt++)
#pragma unroll
            for (int j = 0; j < 4; j++) acc[mt][nt][j] = 0.0f;

    // --- pipeline issue: stage s in [0,48): pass = s>>4, k0 = (s&15)*KS ---
    const int r_ld = tid >> 2;          // 0..63 (+64 for second iter)
    const int c_ld = tid & 3;
#define ISSUE(s) do {                                                          \
    int pass = (s) >> 4, k0 = ((s) & 15) * KS;                                 \
    const __nv_bfloat16* ap = (pass == 2) ? g_lo : g_hi;                       \
    const __nv_bfloat16* bp = (pass == 1) ? g_lo : g_hi;                       \
    uint32_t sbase = sb + ((s) & (NSTG - 1)) * STAGE_BYTES;                    \
    _Pragma("unroll")                                                          \
    for (int it = 0; it < 2; it++) {                                           \
        int r = r_ld + it * 64;                                                \
        uint32_t so = sw_off(r, c_ld);                                         \
        const __nv_bfloat16* ga = ap + (size_t)(i0 + r) * DD + k0 + c_ld * 8;  \
        const __nv_bfloat16* gb = bp + (size_t)(j0 + r) * DD + k0 + c_ld * 8;  \
        CP16(sbase + so, ga);                                                  \
        CP16(sbase + 8192 + so, gb);                                           \
    }                                                                          \
    CP_COMMIT();                                                               \
} while (0)

#pragma unroll
    for (int s = 0; s < NSTG - 1; s++) ISSUE(s);

    for (int s = 0; s < STAGES_TOTAL; s++) {
        CP_WAIT(NSTG - 2);
        __syncthreads();
        if (s + NSTG - 1 < STAGES_TOTAL) ISSUE(s + NSTG - 1);

        const uint32_t sA = sb + (s & (NSTG - 1)) * STAGE_BYTES;
        const uint32_t sB = sA + 8192;
#pragma unroll
        for (int kk = 0; kk < 2; kk++) {
            uint32_t a[4][4], bfr[2][4];
#pragma unroll
            for (int mt = 0; mt < 4; mt++) {
                int r = wm * 64 + mt * 16 + (lane & 15);
                int c = kk * 2 + (lane >> 4);
                LDSM4(a[mt], sA + sw_off(r, c));
            }
#pragma unroll
            for (int nt2 = 0; nt2 < 2; nt2++) {
                int n = wn * 32 + nt2 * 16 + (lane & 7) + ((lane >> 4) << 3);
                int c = kk * 2 + ((lane >> 3) & 1);
                LDSM4(bfr[nt2], sB + sw_off(n, c));
            }
#pragma unroll
            for (int mt = 0; mt < 4; mt++)
#pragma unroll
                for (int nt = 0; nt < 4; nt++) {
                    uint32_t b0 = bfr[nt >> 1][(nt & 1) * 2];
                    uint32_t b1 = bfr[nt >> 1][(nt & 1) * 2 + 1];
                    MMA_BF16(acc[mt][nt], a[mt], b0, b1);
                }
        }
    }

    // ---- epilogue: masked min/max from fragments ----
    int cj[4][2];
#pragma unroll
    for (int nt = 0; nt < 4; nt++) {
        int c0 = wn * 32 + nt * 8 + (lane & 3) * 2;
        cj[nt][0] = tj_s[c0];
        cj[nt][1] = tj_s[c0 + 1];
    }
#pragma unroll
    for (int mt = 0; mt < 4; mt++)
#pragma unroll
        for (int h = 0; h < 2; h++) {
            int rl  = wm * 64 + mt * 16 + (lane >> 2) + h * 8;
            int cls = ti_s[rl];
            float vmin =  3.402823466e38f;
            float vmax = -3.402823466e38f;
#pragma unroll
            for (int nt = 0; nt < 4; nt++) {
                float v0 = acc[mt][nt][h * 2];
                float v1 = acc[mt][nt][h * 2 + 1];
                if (cls == cj[nt][0]) vmin = fminf(vmin, v0); else vmax = fmaxf(vmax, v0);
                if (cls == cj[nt][1]) vmin = fminf(vmin, v1); else vmax = fmaxf(vmax, v1);
            }
#pragma unroll
            for (int off = 1; off < 4; off <<= 1) {
                vmin = fminf(vmin, __shfl_xor_sync(0xffffffffu, vmin, off));
                vmax = fmaxf(vmax, __shfl_xor_sync(0xffffffffu, vmax, off));
            }
            if ((lane & 3) == 0) {
                atomicMin(&g_min_enc[i0 + rl], enc_f(vmin));
                atomicMax(&g_max_enc[i0 + rl], enc_f(vmax));
            }
        }
}

__global__ void loss_kernel(float* __restrict__ out) {
    __shared__ float red[256];
    float s = 0.0f;
    for (int i = threadIdx.x; i < NR; i += 256) {
        float ap = dec_f(g_min_enc[i]);
        float an = dec_f(g_max_enc[i]);
        float v  = an - ap + MARGIN;
        s += (v > 0.0f) ? v : 0.0f;
    }
    red[threadIdx.x] = s;
    __syncthreads();
    for (int o = 128; o > 0; o >>= 1) {
        if (threadIdx.x < o) red[threadIdx.x] += red[threadIdx.x + o];
        __syncthreads();
    }
    if (threadIdx.x == 0) out[0] = red[0] * (1.0f / (float)NR);
}

// ---------------- launch ----------------
extern "C" void kernel_launch(void* const* d_in, const int* in_sizes, int n_in,
                              void* d_out, int out_size) {
    const float* feat    = (const float*)d_in[0];
    const int*   targets = (const int*)d_in[1];
    float*       out     = (float*)d_out;

    cudaFuncSetAttribute(corr_kernel, cudaFuncAttributeMaxDynamicSharedMemorySize,
                         SMEM_TOTAL);

    init_kernel<<<(NR + 255) / 256, 256>>>();
    split_kernel<<<(NR * DD / 4) / 256, 256>>>(feat);
    dim3 grid(NR / BN, NR / BM);   // 32 x 32
    corr_kernel<<<grid, NTH, SMEM_TOTAL>>>(targets);
    loss_kernel<<<1, 256>>>(out);
}

// round 5
// speedup vs baseline: 4.4125x; 1.6863x over previous
#include <cuda_runtime.h>
#include <cuda_bf16.h>
#include <cstdint>

#define NR   4096
#define DD   512
#define BM   128
#define BN   128
#define KS   32                 // bf16 k-elems per pipeline stage
#define NSTG 4
#define NTH  256
#define NPASS 3
#define NBLK (NR / BM)                      // 32
#define NTILES (NBLK * (NBLK + 1) / 2)      // 528
#define STAGES_TOTAL (NPASS * (DD / KS))    // 48
#define STAGE_BYTES  16384      // A 8KB + B 8KB
#define SMEM_LABELS  (NSTG * STAGE_BYTES)   // 65536
#define SMEM_TOTAL   (SMEM_LABELS + 1024)
#define MARGIN 40.0f

// ---------------- device scratch (no allocations allowed) ----------------
__device__ __nv_bfloat16 g_hi[NR * DD];
__device__ __nv_bfloat16 g_lo[NR * DD];
__device__ unsigned g_min_enc[NR];
__device__ unsigned g_max_enc[NR];

// ---------------- helpers ----------------
__device__ __forceinline__ unsigned enc_f(float f) {
    unsigned u = __float_as_uint(f);
    return (u & 0x80000000u) ? ~u : (u | 0x80000000u);
}
__device__ __forceinline__ float dec_f(unsigned e) {
    unsigned u = (e & 0x80000000u) ? (e ^ 0x80000000u) : ~e;
    return __uint_as_float(u);
}
__device__ __forceinline__ uint32_t smem_u32(const void* p) {
    uint32_t a;
    asm("{ .reg .u64 t; cvta.to.shared.u64 t, %1; cvt.u32.u64 %0, t; }" : "=r"(a) : "l"(p));
    return a;
}

#define CP16(smem_addr, gptr) \
    asm volatile("cp.async.cg.shared.global [%0], [%1], 16;" :: "r"(smem_addr), "l"(gptr))
#define CP_COMMIT() asm volatile("cp.async.commit_group;" ::: "memory")
#define CP_WAIT(n)  asm volatile("cp.async.wait_group %0;" :: "n"(n) : "memory")

#define LDSM4(r, addr) \
    asm volatile("ldmatrix.sync.aligned.m8n8.x4.shared.b16 {%0,%1,%2,%3}, [%4];" \
                 : "=r"((r)[0]), "=r"((r)[1]), "=r"((r)[2]), "=r"((r)[3]) : "r"(addr))

#define MMA_BF16(d, a, b0, b1) \
    asm volatile("mma.sync.aligned.m16n8k16.row.col.f32.bf16.bf16.f32 " \
                 "{%0,%1,%2,%3}, {%4,%5,%6,%7}, {%8,%9}, {%0,%1,%2,%3};" \
                 : "+f"((d)[0]), "+f"((d)[1]), "+f"((d)[2]), "+f"((d)[3]) \
                 : "r"((a)[0]), "r"((a)[1]), "r"((a)[2]), "r"((a)[3]), "r"(b0), "r"(b1))

// XOR swizzle: chunk c in {0..3} (16B each) within a 64B row r
__device__ __forceinline__ uint32_t sw_off(int r, int c) {
    return (uint32_t)(r * 64 + ((c ^ ((r >> 1) & 3)) << 4));
}

// ---------------- kernels ----------------
// split + init fused
__global__ void split_kernel(const float* __restrict__ feat) {
    int i = blockIdx.x * blockDim.x + threadIdx.x;   // over N*D/4 float4s
    if (i < NR) {
        g_min_enc[i] = enc_f(3.402823466e38f);
        g_max_enc[i] = enc_f(-3.402823466e38f);
    }
    float4 v = ((const float4*)feat)[i];
    ushort4 h, l;
    __nv_bfloat16 b;
    b = __float2bfloat16(v.x); h.x = __bfloat16_as_ushort(b);
    l.x = __bfloat16_as_ushort(__float2bfloat16(v.x - __bfloat162float(b)));
    b = __float2bfloat16(v.y); h.y = __bfloat16_as_ushort(b);
    l.y = __bfloat16_as_ushort(__float2bfloat16(v.y - __bfloat162float(b)));
    b = __float2bfloat16(v.z); h.z = __bfloat16_as_ushort(b);
    l.z = __bfloat16_as_ushort(__float2bfloat16(v.z - __bfloat162float(b)));
    b = __float2bfloat16(v.w); h.w = __bfloat16_as_ushort(b);
    l.w = __bfloat16_as_ushort(__float2bfloat16(v.w - __bfloat162float(b)));
    ((ushort4*)g_hi)[i] = h;
    ((ushort4*)g_lo)[i] = l;
}

__global__ __launch_bounds__(NTH, 2)
void corr_kernel(const int* __restrict__ targets) {
    extern __shared__ char smem[];
    const uint32_t sb = smem_u32(smem);
    int* ti_s = (int*)(smem + SMEM_LABELS);
    int* tj_s = ti_s + BM;

    // ---- triangular tile decode: tiles with bj >= bi ----
    const int t = blockIdx.x;
    int bi = (int)((65.0f - sqrtf(4225.0f - 8.0f * (float)t)) * 0.5f);
    while (32 * bi - (bi * (bi - 1)) / 2 > t) bi--;
    while (32 * (bi + 1) - ((bi + 1) * bi) / 2 <= t) bi++;
    const int bj = bi + (t - (32 * bi - (bi * (bi - 1)) / 2));
    const int i0 = bi * BM;
    const int j0 = bj * BN;
    const bool diag = (bi == bj);

    const int tid  = threadIdx.x;
    const int lane = tid & 31;
    const int wid  = tid >> 5;
    const int wm   = wid & 1;    // 0..1  (64-row band)
    const int wn   = wid >> 1;   // 0..3  (32-col band)

    if (tid < BM) ti_s[tid] = targets[i0 + tid];
    else          tj_s[tid - BM] = targets[j0 + (tid - BM)];

    float acc[4][4][4];
#pragma unroll
    for (int mt = 0; mt < 4; mt++)
#pragma unroll
        for (int nt = 0; nt < 4; nt++)
#pragma unroll
            for (int j = 0; j < 4; j++) acc[mt][nt][j] = 0.0f;

    // --- pipeline issue: stage s in [0,48): pass = s>>4, k0 = (s&15)*KS ---
    const int r_ld = tid >> 2;          // 0..63 (+64 for second iter)
    const int c_ld = tid & 3;
#define ISSUE(s) do {                                                          \
    int pass = (s) >> 4, k0 = ((s) & 15) * KS;                                 \
    const __nv_bfloat16* ap = (pass == 2) ? g_lo : g_hi;                       \
    const __nv_bfloat16* bp = (pass == 1) ? g_lo : g_hi;                       \
    uint32_t sbase = sb + ((s) & (NSTG - 1)) * STAGE_BYTES;                    \
    _Pragma("unroll")                                                          \
    for (int it = 0; it < 2; it++) {                                           \
        int r = r_ld + it * 64;                                                \
        uint32_t so = sw_off(r, c_ld);                                         \
        const __nv_bfloat16* ga = ap + (size_t)(i0 + r) * DD + k0 + c_ld * 8;  \
        const __nv_bfloat16* gb = bp + (size_t)(j0 + r) * DD + k0 + c_ld * 8;  \
        CP16(sbase + so, ga);                                                  \
        CP16(sbase + 8192 + so, gb);                                           \
    }                                                                          \
    CP_COMMIT();                                                               \
} while (0)

#pragma unroll
    for (int s = 0; s < NSTG - 1; s++) ISSUE(s);

    for (int s = 0; s < STAGES_TOTAL; s++) {
        CP_WAIT(NSTG - 2);
        __syncthreads();
        if (s + NSTG - 1 < STAGES_TOTAL) ISSUE(s + NSTG - 1);

        const uint32_t sA = sb + (s & (NSTG - 1)) * STAGE_BYTES;
        const uint32_t sB = sA + 8192;
#pragma unroll
        for (int kk = 0; kk < 2; kk++) {
            uint32_t a[4][4], bfr[2][4];
#pragma unroll
            for (int mt = 0; mt < 4; mt++) {
                int r = wm * 64 + mt * 16 + (lane & 15);
                int c = kk * 2 + (lane >> 4);
                LDSM4(a[mt], sA + sw_off(r, c));
            }
#pragma unroll
            for (int nt2 = 0; nt2 < 2; nt2++) {
                int n = wn * 32 + nt2 * 16 + (lane & 7) + ((lane >> 4) << 3);
                int c = kk * 2 + ((lane >> 3) & 1);
                LDSM4(bfr[nt2], sB + sw_off(n, c));
            }
#pragma unroll
            for (int mt = 0; mt < 4; mt++)
#pragma unroll
                for (int nt = 0; nt < 4; nt++) {
                    uint32_t b0 = bfr[nt >> 1][(nt & 1) * 2];
                    uint32_t b1 = bfr[nt >> 1][(nt & 1) * 2 + 1];
                    MMA_BF16(acc[mt][nt], a[mt], b0, b1);
                }
        }
    }

    // ---- epilogue: fold fragments into row (and, off-diag, column) min/max ----
    // fragment element (mt, nt, h, p):
    //   row = wm*64 + mt*16 + (lane>>2) + h*8
    //   col = wn*32 + nt*8 + (lane&3)*2 + p
    int clsr[4][2], clsc[4][2];
#pragma unroll
    for (int mt = 0; mt < 4; mt++)
#pragma unroll
        for (int h = 0; h < 2; h++)
            clsr[mt][h] = ti_s[wm * 64 + mt * 16 + (lane >> 2) + h * 8];
#pragma unroll
    for (int nt = 0; nt < 4; nt++)
#pragma unroll
        for (int p = 0; p < 2; p++)
            clsc[nt][p] = tj_s[wn * 32 + nt * 8 + (lane & 3) * 2 + p];

    float rmin[4][2], rmax[4][2], cmin[4][2], cmax[4][2];
#pragma unroll
    for (int a2 = 0; a2 < 4; a2++)
#pragma unroll
        for (int b2 = 0; b2 < 2; b2++) {
            rmin[a2][b2] = 3.402823466e38f;  rmax[a2][b2] = -3.402823466e38f;
            cmin[a2][b2] = 3.402823466e38f;  cmax[a2][b2] = -3.402823466e38f;
        }

#pragma unroll
    for (int mt = 0; mt < 4; mt++)
#pragma unroll
        for (int nt = 0; nt < 4; nt++)
#pragma unroll
            for (int h = 0; h < 2; h++)
#pragma unroll
                for (int p = 0; p < 2; p++) {
                    float v = acc[mt][nt][h * 2 + p];
                    if (clsr[mt][h] == clsc[nt][p]) {
                        rmin[mt][h] = fminf(rmin[mt][h], v);
                        cmin[nt][p] = fminf(cmin[nt][p], v);
                    } else {
                        rmax[mt][h] = fmaxf(rmax[mt][h], v);
                        cmax[nt][p] = fmaxf(cmax[nt][p], v);
                    }
                }

    // row reduction across the 4 lanes of each quad-row group (xor 1, 2)
#pragma unroll
    for (int mt = 0; mt < 4; mt++)
#pragma unroll
        for (int h = 0; h < 2; h++) {
            float vmin = rmin[mt][h], vmax = rmax[mt][h];
#pragma unroll
            for (int off = 1; off < 4; off <<= 1) {
                vmin = fminf(vmin, __shfl_xor_sync(0xffffffffu, vmin, off));
                vmax = fmaxf(vmax, __shfl_xor_sync(0xffffffffu, vmax, off));
            }
            if ((lane & 3) == 0) {
                int rl = wm * 64 + mt * 16 + (lane >> 2) + h * 8;
                atomicMin(&g_min_enc[i0 + rl], enc_f(vmin));
                atomicMax(&g_max_enc[i0 + rl], enc_f(vmax));
            }
        }

    // column reduction across the 8 row-groups (xor 4, 8, 16) — off-diagonal only
    if (!diag) {
#pragma unroll
        for (int nt = 0; nt < 4; nt++)
#pragma unroll
            for (int p = 0; p < 2; p++) {
                float vmin = cmin[nt][p], vmax = cmax[nt][p];
#pragma unroll
                for (int off = 4; off < 32; off <<= 1) {
                    vmin = fminf(vmin, __shfl_xor_sync(0xffffffffu, vmin, off));
                    vmax = fmaxf(vmax, __shfl_xor_sync(0xffffffffu, vmax, off));
                }
                if ((lane >> 2) == 0) {
                    int cl = wn * 32 + nt * 8 + (lane & 3) * 2 + p;
                    atomicMin(&g_min_enc[j0 + cl], enc_f(vmin));
                    atomicMax(&g_max_enc[j0 + cl], enc_f(vmax));
                }
            }
    }
}

__global__ void loss_kernel(float* __restrict__ out) {
    __shared__ float red[256];
    float s = 0.0f;
#pragma unroll
    for (int it = 0; it < NR / (256 * 4); it++) {
        int i = (it * 256 + threadIdx.x);
        uint4 mn = ((const uint4*)g_min_enc)[i];
        uint4 mx = ((const uint4*)g_max_enc)[i];
        float v;
        v = dec_f(mx.x) - dec_f(mn.x) + MARGIN; s += fmaxf(v, 0.0f);
        v = dec_f(mx.y) - dec_f(mn.y) + MARGIN; s += fmaxf(v, 0.0f);
        v = dec_f(mx.z) - dec_f(mn.z) + MARGIN; s += fmaxf(v, 0.0f);
        v = dec_f(mx.w) - dec_f(mn.w) + MARGIN; s += fmaxf(v, 0.0f);
    }
    red[threadIdx.x] = s;
    __syncthreads();
    for (int o = 128; o > 32; o >>= 1) {
        if (threadIdx.x < o) red[threadIdx.x] += red[threadIdx.x + o];
        __syncthreads();
    }
    if (threadIdx.x < 32) {
        float v = red[threadIdx.x] + red[threadIdx.x + 32];
#pragma unroll
        for (int off = 16; off > 0; off >>= 1)
            v += __shfl_xor_sync(0xffffffffu, v, off);
        if (threadIdx.x == 0) out[0] = v * (1.0f / (float)NR);
    }
}

// ---------------- launch ----------------
extern "C" void kernel_launch(void* const* d_in, const int* in_sizes, int n_in,
                              void* d_out, int out_size) {
    const float* feat    = (const float*)d_in[0];
    const int*   targets = (const int*)d_in[1];
    float*       out     = (float*)d_out;

    cudaFuncSetAttribute(corr_kernel, cudaFuncAttributeMaxDynamicSharedMemorySize,
                         SMEM_TOTAL);

    split_kernel<<<(NR * DD / 4) / 256, 256>>>(feat);
    corr_kernel<<<NTILES, NTH, SMEM_TOTAL>>>(targets);
    loss_kernel<<<1, 256>>>(out);
}